// round 2
// baseline (speedup 1.0000x reference)
#include <cuda_runtime.h>
#include <cuda_bf16.h>

#define NN 50000
#define NE 400000
#define H  256
#define ED 768
#define NL 6
#define NEG_SLOPE 0.2f

// ---------------- device scratch (no cudaMalloc allowed) ----------------
__device__ float g_h [NN * H];
__device__ float g_hp[NN * H];
__device__ float g_o [NN * H];
__device__ float g_W12[H * H];
__device__ float g_W3f[H * H];
__device__ float g_us[NL * H];
__device__ float g_ud[NL * H];
__device__ float g_ve[NL * ED];
__device__ float g_esc[NL * NE];
__device__ float g_alpha[NE];
__device__ float g_ea[NE];
__device__ float g_s[NN];
__device__ float g_d[NN];
__device__ int   g_mmax[NN];
__device__ float g_den[NN];
__device__ int   g_is64;

// ---------------- helpers ----------------
__device__ __forceinline__ int f2ord(float f) {
    int i = __float_as_int(f);
    return (i >= 0) ? i : (i ^ 0x7FFFFFFF);
}
__device__ __forceinline__ float ord2f(int i) {
    return (i >= 0) ? __int_as_float(i) : __int_as_float(i ^ 0x7FFFFFFF);
}
__device__ __forceinline__ long long fetch_idx(const void* ei, long long i, int is64) {
    if (is64) return ((const long long*)ei)[i];
    return (long long)((const int*)ei)[i];
}

// Detect whether edge_index is int64 or int32: if int64 (values < 2^31),
// every odd 32-bit word is 0. 512 samples of random indices in [0,50000)
// being all zero under int32 is impossible.
__global__ void kDetect(const int* __restrict__ ei) {
    if (blockIdx.x == 0 && threadIdx.x == 0) {
        int nz = 0;
        for (int i = 0; i < 512; i++) nz |= ei[2 * i + 1];
        g_is64 = (nz == 0) ? 1 : 0;
    }
}

// W12 = W1 @ W2   (256x256 @ 256x256)
__global__ void kW12(const float* __restrict__ W1, const float* __restrict__ W2) {
    int r = blockIdx.x, n = threadIdx.x;
    float acc = 0.f;
    for (int k = 0; k < H; k++) acc += W1[r * H + k] * W2[k * H + n];
    g_W12[r * H + n] = acc;
}

// W3f = W3[0:256] + W3[256:512]   (exact fold of relu(concat(h,h)) @ W3)
__global__ void kW3f(const float* __restrict__ W3) {
    int r = blockIdx.x, n = threadIdx.x;
    g_W3f[r * H + n] = W3[r * H + n] + W3[(H + r) * H + n];
}

// u_s[l][k] = sum_j Wc[l][k][j] * a_s[l][j]   (and same for u_d)
__global__ void kUsUd(const float* __restrict__ Wc, const float* __restrict__ as,
                      const float* __restrict__ ad) {
    int l = blockIdx.x / H, k = blockIdx.x % H;
    int j = threadIdx.x;
    float w = Wc[((size_t)l * H + k) * H + j];
    __shared__ float ss[H], sd[H];
    ss[j] = w * as[l * H + j];
    sd[j] = w * ad[l * H + j];
    __syncthreads();
    for (int st = 128; st > 0; st >>= 1) {
        if (j < st) { ss[j] += ss[j + st]; sd[j] += sd[j + st]; }
        __syncthreads();
    }
    if (j == 0) { g_us[l * H + k] = ss[0]; g_ud[l * H + k] = sd[0]; }
}

// v_e[l][k] = sum_j We[l][k][j] * a_e[l][j]
__global__ void kVe(const float* __restrict__ We, const float* __restrict__ ae) {
    int l = blockIdx.x / ED, k = blockIdx.x % ED;
    int j = threadIdx.x;
    __shared__ float ss[H];
    ss[j] = We[((size_t)l * ED + k) * H + j] * ae[l * H + j];
    __syncthreads();
    for (int st = 128; st > 0; st >>= 1) {
        if (j < st) ss[j] += ss[j + st];
        __syncthreads();
    }
    if (j == 0) g_ve[l * ED + k] = ss[0];
}

// Edge scores for ALL 6 layers in one pass over edge_attr (1.23 GB):
// esc[l][e] = edge_attr[e] . v_e[l]
__global__ void kEsc(const float* __restrict__ eattr) {
    __shared__ float sV[NL * ED];   // 18 KB
    for (int i = threadIdx.x; i < NL * ED; i += blockDim.x) sV[i] = g_ve[i];
    __syncthreads();
    int warp = threadIdx.x >> 5, lane = threadIdx.x & 31;
    int e = blockIdx.x * 8 + warp;
    if (e >= NE) return;
    const float* row = eattr + (size_t)e * ED;
    float acc[NL] = {0, 0, 0, 0, 0, 0};
    for (int j = lane; j < ED; j += 32) {
        float a = row[j];
#pragma unroll
        for (int l = 0; l < NL; l++) acc[l] += a * sV[l * ED + j];
    }
#pragma unroll
    for (int l = 0; l < NL; l++) {
        float v = acc[l];
        for (int off = 16; off; off >>= 1) v += __shfl_down_sync(0xffffffffu, v, off);
        if (lane == 0) g_esc[(size_t)l * NE + e] = v;
    }
}

// fp32 SGEMM: C[M,256] = (reluA ? relu(A) : A)[M,256] @ B[256,256]
// BM=128, BN=64, BK=16, 256 threads, 8x4 per thread.
__global__ void sgemm(const float* __restrict__ A, const float* __restrict__ B,
                      float* __restrict__ C, int M, int reluA) {
    __shared__ float As[16][129];
    __shared__ float Bs[16][64];
    int tid = threadIdx.x;
    int tx = tid & 15;           // output col group
    int ty = tid >> 4;           // output row group
    int rowBase = blockIdx.y * 128;
    int colBase = blockIdx.x * 64;
    int ar = tid >> 2;           // 0..63
    int ac = (tid & 3) << 2;     // 0,4,8,12
    int br = tid >> 4;           // 0..15
    int bc = (tid & 15) << 2;

    float acc[8][4];
#pragma unroll
    for (int i = 0; i < 8; i++)
#pragma unroll
        for (int j = 0; j < 4; j++) acc[i][j] = 0.f;

    for (int k0 = 0; k0 < H; k0 += 16) {
#pragma unroll
        for (int rr = 0; rr < 2; rr++) {
            int r = rowBase + ar + rr * 64;
            float4 av = make_float4(0.f, 0.f, 0.f, 0.f);
            if (r < M) av = *(const float4*)(A + (size_t)r * H + k0 + ac);
            if (reluA) {
                av.x = fmaxf(av.x, 0.f); av.y = fmaxf(av.y, 0.f);
                av.z = fmaxf(av.z, 0.f); av.w = fmaxf(av.w, 0.f);
            }
            As[ac + 0][ar + rr * 64] = av.x;
            As[ac + 1][ar + rr * 64] = av.y;
            As[ac + 2][ar + rr * 64] = av.z;
            As[ac + 3][ar + rr * 64] = av.w;
        }
        float4 bv = *(const float4*)(B + (size_t)(k0 + br) * H + colBase + bc);
        *(float4*)&Bs[br][bc] = bv;
        __syncthreads();
#pragma unroll
        for (int k = 0; k < 16; k++) {
            float a[8], b[4];
#pragma unroll
            for (int i = 0; i < 8; i++) a[i] = As[k][ty * 8 + i];
            float4 bq = *(const float4*)&Bs[k][tx * 4];
            b[0] = bq.x; b[1] = bq.y; b[2] = bq.z; b[3] = bq.w;
#pragma unroll
            for (int i = 0; i < 8; i++)
#pragma unroll
                for (int j = 0; j < 4; j++) acc[i][j] += a[i] * b[j];
        }
        __syncthreads();
    }
#pragma unroll
    for (int i = 0; i < 8; i++) {
        int r = rowBase + ty * 8 + i;
        if (r < M) {
            float4 ov = make_float4(acc[i][0], acc[i][1], acc[i][2], acc[i][3]);
            *(float4*)(C + (size_t)r * H + colBase + tx * 4) = ov;
        }
    }
}

// s[n] = h[n] . u_s[l],  d[n] = h[n] . u_d[l]
__global__ void kSD(const float* __restrict__ h, int l) {
    int warp = threadIdx.x >> 5, lane = threadIdx.x & 31;
    int n = blockIdx.x * 8 + warp;
    if (n >= NN) return;
    const float* row = h + (size_t)n * H;
    const float* us = g_us + l * H;
    const float* ud = g_ud + l * H;
    float s = 0.f, d = 0.f;
    for (int j = lane; j < H; j += 32) {
        float v = row[j];
        s += v * us[j];
        d += v * ud[j];
    }
    for (int off = 16; off; off >>= 1) {
        s += __shfl_down_sync(0xffffffffu, s, off);
        d += __shfl_down_sync(0xffffffffu, d, off);
    }
    if (lane == 0) { g_s[n] = s; g_d[n] = d; }
}

// out[n] = bias; mmax = -inf (ordered-int); den = 0
__global__ void kInit(const float* __restrict__ bias, float* __restrict__ out) {
    int n = blockIdx.x, c = threadIdx.x;
    out[(size_t)n * H + c] = bias[c];
    if (c == 0) { g_mmax[n] = (int)0x80000000; g_den[n] = 0.f; }
}

// alpha[e] = leaky_relu(s[src]+d[dst]+esc[l][e]); segment-max into mmax[dst]
__global__ void kAlpha(const void* __restrict__ ei, int l) {
    int e = blockIdx.x * 256 + threadIdx.x;
    if (e >= NE) return;
    int is64 = g_is64;
    long long src = fetch_idx(ei, e, is64);
    long long dst = fetch_idx(ei, (long long)NE + e, is64);
    float a = g_s[src] + g_d[dst] + g_esc[(size_t)l * NE + e];
    a = (a > 0.f) ? a : NEG_SLOPE * a;
    g_alpha[e] = a;
    atomicMax(&g_mmax[dst], f2ord(a));
}

// ea[e] = exp(alpha - m[dst]); den[dst] += ea
__global__ void kEa(const void* __restrict__ ei) {
    int e = blockIdx.x * 256 + threadIdx.x;
    if (e >= NE) return;
    int is64 = g_is64;
    long long dst = fetch_idx(ei, (long long)NE + e, is64);
    float m = ord2f(g_mmax[dst]);
    float ea = expf(g_alpha[e] - m);
    g_ea[e] = ea;
    atomicAdd(&g_den[dst], ea);
}

// out[dst] += hp[src] * (ea/(den[dst]+1e-16));  64 threads per edge, float4 gather
__global__ void kAgg(const void* __restrict__ ei, float* __restrict__ out,
                     const float* __restrict__ hp) {
    int t = threadIdx.x;
    int e = blockIdx.x * 4 + (t >> 6);
    int lane = t & 63;
    if (e >= NE) return;
    int is64 = g_is64;
    long long src = fetch_idx(ei, e, is64);
    long long dst = fetch_idx(ei, (long long)NE + e, is64);
    float coef = g_ea[e] / (g_den[dst] + 1e-16f);
    float4 v = *(const float4*)(hp + (size_t)src * H + lane * 4);
    float* o = out + (size_t)dst * H + lane * 4;
    atomicAdd(o + 0, v.x * coef);
    atomicAdd(o + 1, v.y * coef);
    atomicAdd(o + 2, v.z * coef);
    atomicAdd(o + 3, v.w * coef);
}

// ---------------- launch ----------------
extern "C" void kernel_launch(void* const* d_in, const int* in_sizes, int n_in,
                              void* d_out, int out_size) {
    const float* x     = (const float*)d_in[0];
    const void*  ei    = d_in[1];
    const float* eattr = (const float*)d_in[2];
    const float* W1    = (const float*)d_in[3];
    const float* W2    = (const float*)d_in[4];
    const float* Wc    = (const float*)d_in[5];
    const float* We    = (const float*)d_in[6];
    const float* as    = (const float*)d_in[7];
    const float* ad    = (const float*)d_in[8];
    const float* ae    = (const float*)d_in[9];
    const float* bias  = (const float*)d_in[10];
    const float* W3    = (const float*)d_in[11];

    float *h, *hp, *o, *w12, *w3f;
    cudaGetSymbolAddress((void**)&h,   g_h);
    cudaGetSymbolAddress((void**)&hp,  g_hp);
    cudaGetSymbolAddress((void**)&o,   g_o);
    cudaGetSymbolAddress((void**)&w12, g_W12);
    cudaGetSymbolAddress((void**)&w3f, g_W3f);

    kDetect<<<1, 32>>>((const int*)ei);
    kW12<<<H, H>>>(W1, W2);
    kW3f<<<H, H>>>(W3);
    kUsUd<<<NL * H, H>>>(Wc, as, ad);
    kVe<<<NL * ED, H>>>(We, ae);
    kEsc<<<(NE + 7) / 8, 256>>>(eattr);

    dim3 ggrid(H / 64, (NN + 127) / 128);
    sgemm<<<ggrid, 256>>>(x, w12, h, NN, 0);           // h = x @ (W1@W2)

    for (int l = 0; l < NL; l++) {
        sgemm<<<ggrid, 256>>>(h, Wc + (size_t)l * H * H, hp, NN, 0);  // h' = h@Wc
        kSD<<<(NN + 7) / 8, 256>>>(h, l);
        kInit<<<NN, H>>>(bias + (size_t)l * H, o);
        kAlpha<<<(NE + 255) / 256, 256>>>(ei, l);
        kEa<<<(NE + 255) / 256, 256>>>(ei);
        kAgg<<<(NE + 3) / 4, 256>>>(ei, o, hp);
        float* tmp = h; h = o; o = tmp;
    }

    sgemm<<<ggrid, 256>>>(h, w3f, (float*)d_out, NN, 1);  // relu(h) @ (W3a+W3b)
}

// round 6
// speedup vs baseline: 1.9617x; 1.9617x over previous
#include <cuda_runtime.h>
#include <cuda_bf16.h>
#include <cstdint>

#define NN 50000
#define NE 400000
#define H  256
#define ED 768
#define NL 6
#define NEG_SLOPE 0.2f

// ---------------- device scratch ----------------
__device__ __align__(16) float g_h [NN * H];
__device__ __align__(16) float g_hp[NN * H];
__device__ __align__(16) float g_o [NN * H];
__device__ __align__(16) float g_W12[H * H];
__device__ __align__(16) float g_W3f[H * H];
__device__ float g_us[NL * H];
__device__ float g_ud[NL * H];
__device__ __align__(16) float g_ve[NL * ED];
__device__ float g_esc[NL * NE];
__device__ float g_alpha[NE];
__device__ float g_s[NN];
__device__ float g_d[NN];
__device__ int   g_is64;
__device__ __align__(16) __nv_bfloat16 g_ahi[NN * H];
__device__ __align__(16) __nv_bfloat16 g_alo[NN * H];
__device__ __align__(16) __nv_bfloat16 g_bhi[8 * H * H];
__device__ __align__(16) __nv_bfloat16 g_blo[8 * H * H];
__device__ int g_deg[NN];
__device__ int g_off[NN + 1];
__device__ int g_cur[NN];
__device__ int g_eid[NE];

// ---------------- helpers ----------------
__device__ __forceinline__ long long fetch_idx(const void* ei, long long i, int is64) {
    if (is64) return ((const long long*)ei)[i];
    return (long long)((const int*)ei)[i];
}
__device__ __forceinline__ uint32_t smem_u32(const void* p) {
    uint32_t a;
    asm("{ .reg .u64 t; cvta.to.shared.u64 t, %1; cvt.u32.u64 %0, t; }" : "=r"(a) : "l"(p));
    return a;
}

#define LDM_X4(r, a) \
    asm volatile("ldmatrix.sync.aligned.m8n8.x4.shared.b16 {%0,%1,%2,%3}, [%4];" \
        : "=r"((r)[0]), "=r"((r)[1]), "=r"((r)[2]), "=r"((r)[3]) : "r"(a))

#define MMA16816(d, a, b0, b1) \
    asm volatile("mma.sync.aligned.m16n8k16.row.col.f32.bf16.bf16.f32 " \
        "{%0,%1,%2,%3}, {%4,%5,%6,%7}, {%8,%9}, {%0,%1,%2,%3};" \
        : "+f"((d)[0]), "+f"((d)[1]), "+f"((d)[2]), "+f"((d)[3]) \
        : "r"((a)[0]), "r"((a)[1]), "r"((a)[2]), "r"((a)[3]), "r"(b0), "r"(b1))

// ---------------- tiny prep kernels ----------------
__global__ void kDetect(const int* __restrict__ ei) {
    if (blockIdx.x == 0 && threadIdx.x == 0) {
        int nz = 0;
        for (int i = 0; i < 512; i++) nz |= ei[2 * i + 1];
        g_is64 = (nz == 0) ? 1 : 0;
    }
}

__global__ void kW12(const float* __restrict__ W1, const float* __restrict__ W2) {
    int r = blockIdx.x, n = threadIdx.x;
    float acc = 0.f;
    for (int k = 0; k < H; k++) acc += W1[r * H + k] * W2[k * H + n];
    g_W12[r * H + n] = acc;
}

__global__ void kW3f(const float* __restrict__ W3) {
    int r = blockIdx.x, n = threadIdx.x;
    g_W3f[r * H + n] = W3[r * H + n] + W3[(H + r) * H + n];
}

__global__ void kUsUd(const float* __restrict__ Wc, const float* __restrict__ as,
                      const float* __restrict__ ad) {
    int l = blockIdx.x / H, k = blockIdx.x % H;
    int j = threadIdx.x;
    float w = Wc[((size_t)l * H + k) * H + j];
    __shared__ float ss[H], sd[H];
    ss[j] = w * as[l * H + j];
    sd[j] = w * ad[l * H + j];
    __syncthreads();
    for (int st = 128; st > 0; st >>= 1) {
        if (j < st) { ss[j] += ss[j + st]; sd[j] += sd[j + st]; }
        __syncthreads();
    }
    if (j == 0) { g_us[l * H + k] = ss[0]; g_ud[l * H + k] = sd[0]; }
}

__global__ void kVe(const float* __restrict__ We, const float* __restrict__ ae) {
    int l = blockIdx.x / ED, k = blockIdx.x % ED;
    int j = threadIdx.x;
    __shared__ float ss[H];
    ss[j] = We[((size_t)l * ED + k) * H + j] * ae[l * H + j];
    __syncthreads();
    for (int st = 128; st > 0; st >>= 1) {
        if (j < st) ss[j] += ss[j + st];
        __syncthreads();
    }
    if (j == 0) g_ve[l * ED + k] = ss[0];
}

// Edge scores for all 6 layers, one float4 pass over edge_attr (1.23 GB)
__global__ void kEsc(const float* __restrict__ eattr) {
    __shared__ float sV[NL * ED];
    for (int i = threadIdx.x; i < NL * ED; i += blockDim.x) sV[i] = g_ve[i];
    __syncthreads();
    int warp = threadIdx.x >> 5, lane = threadIdx.x & 31;
    int e = blockIdx.x * 8 + warp;
    if (e >= NE) return;
    const float4* row = (const float4*)(eattr + (size_t)e * ED);
    float acc[NL] = {0, 0, 0, 0, 0, 0};
#pragma unroll
    for (int it = 0; it < ED / 128; it++) {
        int j4 = it * 32 + lane;           // float4 index within row
        float4 a = row[j4];
        int j = j4 * 4;
#pragma unroll
        for (int l = 0; l < NL; l++) {
            const float* v = sV + l * ED + j;
            acc[l] += a.x * v[0] + a.y * v[1] + a.z * v[2] + a.w * v[3];
        }
    }
#pragma unroll
    for (int l = 0; l < NL; l++) {
        float v = acc[l];
        for (int off = 16; off; off >>= 1) v += __shfl_down_sync(0xffffffffu, v, off);
        if (lane == 0) g_esc[(size_t)l * NE + e] = v;
    }
}

// transpose + bf16 split of a 256x256 weight: Bop[n][k] = W[k][n]
__global__ void kSplitWT(const float* __restrict__ W, int bi) {
    int n = blockIdx.x, k = threadIdx.x;
    float v = W[k * H + n];
    __nv_bfloat16 hb = __float2bfloat16(v);
    __nv_bfloat16 lb = __float2bfloat16(v - __bfloat162float(hb));
    size_t o = (size_t)bi * H * H + (size_t)n * H + k;
    g_bhi[o] = hb;
    g_blo[o] = lb;
}

// fp32 activations -> bf16 hi/lo splits (optionally fused relu)
__global__ void kSplitA(const float* __restrict__ src, int relu) {
    size_t i = ((size_t)blockIdx.x * 256 + threadIdx.x) * 8;
    if (i >= (size_t)NN * H) return;
    float v[8];
    *(float4*)(v)     = *(const float4*)(src + i);
    *(float4*)(v + 4) = *(const float4*)(src + i + 4);
    union { __nv_bfloat16 b[8]; uint4 u; } hh, ll;
#pragma unroll
    for (int j = 0; j < 8; j++) {
        float x = relu ? fmaxf(v[j], 0.f) : v[j];
        __nv_bfloat16 hb = __float2bfloat16(x);
        hh.b[j] = hb;
        ll.b[j] = __float2bfloat16(x - __bfloat162float(hb));
    }
    *(uint4*)(g_ahi + i) = hh.u;
    *(uint4*)(g_alo + i) = ll.u;
}

// ---------------- mma.sync bf16 3-split GEMM ----------------
// C[M,256] = (Ahi+Alo)[M,256] @ (Bhi+Blo)^T   where Bop[n][k] = W[k][n]
#define BM 128
#define BN 128
#define BK 32
#define PAD 40   // bf16 elems per smem row (80 B): ldmatrix conflict-free

__global__ void __launch_bounds__(256, 2) gemm_mma(
    const __nv_bfloat16* __restrict__ Ah, const __nv_bfloat16* __restrict__ Al,
    const __nv_bfloat16* __restrict__ Bh, const __nv_bfloat16* __restrict__ Bl,
    float* __restrict__ C, int M) {
    __shared__ __nv_bfloat16 sAh[BM * PAD], sAl[BM * PAD];
    __shared__ __nv_bfloat16 sBh[BN * PAD], sBl[BN * PAD];
    int tid = threadIdx.x, wid = tid >> 5, lane = tid & 31;
    int wm = wid & 3, wn = wid >> 2;             // warp tile: rows wm*32, cols wn*64
    int m0 = blockIdx.y * BM, n0 = blockIdx.x * BN;

    float acc[2][8][4];
#pragma unroll
    for (int i = 0; i < 2; i++)
#pragma unroll
        for (int j = 0; j < 8; j++)
#pragma unroll
            for (int q = 0; q < 4; q++) acc[i][j][q] = 0.f;

    int grp = lane >> 3, lr = lane & 7;
    int rowoff = lr + 8 * (grp & 1);
    int csel = grp >> 1;                          // 16B chunk select within kstep

    for (int k0 = 0; k0 < H; k0 += BK) {
        // ---- global -> smem (512 uint4 per tile, 2 per thread) ----
#pragma unroll
        for (int it = 0; it < 2; it++) {
            int idx = tid + it * 256;
            int r = idx >> 2, c = idx & 3;
            int gr = m0 + r;
            uint4 vh = make_uint4(0, 0, 0, 0), vl = vh;
            if (gr < M) {
                vh = *((const uint4*)(Ah + (size_t)gr * H + k0) + c);
                vl = *((const uint4*)(Al + (size_t)gr * H + k0) + c);
            }
            *(uint4*)(sAh + r * PAD + c * 8) = vh;
            *(uint4*)(sAl + r * PAD + c * 8) = vl;
            *(uint4*)(sBh + r * PAD + c * 8) = *((const uint4*)(Bh + (size_t)(n0 + r) * H + k0) + c);
            *(uint4*)(sBl + r * PAD + c * 8) = *((const uint4*)(Bl + (size_t)(n0 + r) * H + k0) + c);
        }
        __syncthreads();

#pragma unroll
        for (int s = 0; s < 3; s++) {
            const __nv_bfloat16* As = (s == 2) ? sAl : sAh;
            const __nv_bfloat16* Bs = (s == 1) ? sBl : sBh;
#pragma unroll
            for (int ks = 0; ks < 2; ks++) {
                int chunk = ks * 2 + csel;
                uint32_t af[2][4], bf[4][4];
#pragma unroll
                for (int mt = 0; mt < 2; mt++) {
                    uint32_t a = smem_u32(As + (wm * 32 + mt * 16 + rowoff) * PAD + chunk * 8);
                    LDM_X4(af[mt], a);
                }
#pragma unroll
                for (int nt = 0; nt < 4; nt++) {
                    uint32_t a = smem_u32(Bs + (wn * 64 + nt * 16 + rowoff) * PAD + chunk * 8);
                    LDM_X4(bf[nt], a);
                }
#pragma unroll
                for (int mt = 0; mt < 2; mt++)
#pragma unroll
                    for (int nt = 0; nt < 4; nt++) {
                        MMA16816(acc[mt][nt * 2 + 0], af[mt], bf[nt][0], bf[nt][2]);
                        MMA16816(acc[mt][nt * 2 + 1], af[mt], bf[nt][1], bf[nt][3]);
                    }
            }
        }
        __syncthreads();
    }

    // ---- store ----
#pragma unroll
    for (int mt = 0; mt < 2; mt++) {
        int gr = m0 + wm * 32 + mt * 16 + (lane >> 2);
#pragma unroll
        for (int nt = 0; nt < 8; nt++) {
            int gc = n0 + wn * 64 + nt * 8 + (lane & 3) * 2;
            if (gr < M)
                *(float2*)(C + (size_t)gr * H + gc) = make_float2(acc[mt][nt][0], acc[mt][nt][1]);
            if (gr + 8 < M)
                *(float2*)(C + (size_t)(gr + 8) * H + gc) = make_float2(acc[mt][nt][2], acc[mt][nt][3]);
        }
    }
}

// ---------------- CSR build ----------------
__global__ void kDeg0() {
    int n = blockIdx.x * 256 + threadIdx.x;
    if (n < NN) g_deg[n] = 0;
}
__global__ void kHist(const void* __restrict__ ei) {
    int e = blockIdx.x * 256 + threadIdx.x;
    if (e >= NE) return;
    long long d = fetch_idx(ei, (long long)NE + e, g_is64);
    atomicAdd(&g_deg[(int)d], 1);
}
__global__ void kScan() {
    __shared__ int ssum[1024];
    int t = threadIdx.x;
    const int per = (NN + 1023) / 1024;
    int b0 = t * per;
    int s = 0;
    for (int i = 0; i < per; i++) {
        int n = b0 + i;
        if (n < NN) s += g_deg[n];
    }
    ssum[t] = s;
    __syncthreads();
    for (int st = 1; st < 1024; st <<= 1) {
        int v = (t >= st) ? ssum[t - st] : 0;
        __syncthreads();
        ssum[t] += v;
        __syncthreads();
    }
    int pre = (t == 0) ? 0 : ssum[t - 1];
    for (int i = 0; i < per; i++) {
        int n = b0 + i;
        if (n < NN) {
            g_off[n] = pre;
            g_cur[n] = pre;
            pre += g_deg[n];
        }
    }
    if (t == 1023) g_off[NN] = ssum[1023];
}
__global__ void kScatter(const void* __restrict__ ei) {
    int e = blockIdx.x * 256 + threadIdx.x;
    if (e >= NE) return;
    long long d = fetch_idx(ei, (long long)NE + e, g_is64);
    int p = atomicAdd(&g_cur[(int)d], 1);
    g_eid[p] = e;
}

// ---------------- per-layer kernels ----------------
__global__ void kSD(const float* __restrict__ h, int l) {
    int warp = threadIdx.x >> 5, lane = threadIdx.x & 31;
    int n = blockIdx.x * 8 + warp;
    if (n >= NN) return;
    const float* row = h + (size_t)n * H;
    const float* us = g_us + l * H;
    const float* ud = g_ud + l * H;
    float s = 0.f, d = 0.f;
    for (int j = lane; j < H; j += 32) {
        float v = row[j];
        s += v * us[j];
        d += v * ud[j];
    }
    for (int off = 16; off; off >>= 1) {
        s += __shfl_down_sync(0xffffffffu, s, off);
        d += __shfl_down_sync(0xffffffffu, d, off);
    }
    if (lane == 0) { g_s[n] = s; g_d[n] = d; }
}

__global__ void kAlpha(const void* __restrict__ ei, int l) {
    int e = blockIdx.x * 256 + threadIdx.x;
    if (e >= NE) return;
    int is64 = g_is64;
    long long src = fetch_idx(ei, e, is64);
    long long dst = fetch_idx(ei, (long long)NE + e, is64);
    float a = g_s[src] + g_d[dst] + g_esc[(size_t)l * NE + e];
    a = (a > 0.f) ? a : NEG_SLOPE * a;
    g_alpha[e] = a;
}

// fused segment softmax + weighted aggregation (warp per node, no atomics)
__global__ void kGat(const void* __restrict__ ei, const float* __restrict__ hp,
                     float* __restrict__ out, const float* __restrict__ bias) {
    int warp = threadIdx.x >> 5, lane = threadIdx.x & 31;
    int n = blockIdx.x * 8 + warp;
    if (n >= NN) return;
    int is64 = g_is64;
    int beg = g_off[n], end = g_off[n + 1];
    float m = -1e30f;
    for (int j = beg; j < end; j++) m = fmaxf(m, g_alpha[g_eid[j]]);
    float4 a0 = make_float4(0, 0, 0, 0), a1 = make_float4(0, 0, 0, 0);
    float den = 0.f;
    for (int j = beg; j < end; j++) {
        int e = g_eid[j];
        float w = expf(g_alpha[e] - m);
        den += w;
        long long src = fetch_idx(ei, e, is64);
        const float4* r = (const float4*)(hp + (size_t)src * H);
        float4 v0 = r[lane], v1 = r[lane + 32];
        a0.x += w * v0.x; a0.y += w * v0.y; a0.z += w * v0.z; a0.w += w * v0.w;
        a1.x += w * v1.x; a1.y += w * v1.y; a1.z += w * v1.z; a1.w += w * v1.w;
    }
    float sc = 1.f / (den + 1e-16f);
    const float4* b = (const float4*)bias;
    float4 b0 = b[lane], b1 = b[lane + 32];
    float4* dst = (float4*)(out + (size_t)n * H);
    dst[lane]      = make_float4(a0.x * sc + b0.x, a0.y * sc + b0.y,
                                 a0.z * sc + b0.z, a0.w * sc + b0.w);
    dst[lane + 32] = make_float4(a1.x * sc + b1.x, a1.y * sc + b1.y,
                                 a1.z * sc + b1.z, a1.w * sc + b1.w);
}

// ---------------- launch ----------------
extern "C" void kernel_launch(void* const* d_in, const int* in_sizes, int n_in,
                              void* d_out, int out_size) {
    const float* x     = (const float*)d_in[0];
    const void*  ei    = d_in[1];
    const float* eattr = (const float*)d_in[2];
    const float* W1    = (const float*)d_in[3];
    const float* W2    = (const float*)d_in[4];
    const float* Wc    = (const float*)d_in[5];
    const float* We    = (const float*)d_in[6];
    const float* as    = (const float*)d_in[7];
    const float* ad    = (const float*)d_in[8];
    const float* ae    = (const float*)d_in[9];
    const float* bias  = (const float*)d_in[10];
    const float* W3    = (const float*)d_in[11];

    float *h, *hp, *o, *w12, *w3f;
    __nv_bfloat16 *ahi, *alo, *bhi, *blo;
    cudaGetSymbolAddress((void**)&h,   g_h);
    cudaGetSymbolAddress((void**)&hp,  g_hp);
    cudaGetSymbolAddress((void**)&o,   g_o);
    cudaGetSymbolAddress((void**)&w12, g_W12);
    cudaGetSymbolAddress((void**)&w3f, g_W3f);
    cudaGetSymbolAddress((void**)&ahi, g_ahi);
    cudaGetSymbolAddress((void**)&alo, g_alo);
    cudaGetSymbolAddress((void**)&bhi, g_bhi);
    cudaGetSymbolAddress((void**)&blo, g_blo);

    kDetect<<<1, 32>>>((const int*)ei);
    kW12<<<H, H>>>(W1, W2);
    kW3f<<<H, H>>>(W3);
    kUsUd<<<NL * H, H>>>(Wc, as, ad);
    kVe<<<NL * ED, H>>>(We, ae);
    kEsc<<<(NE + 7) / 8, 256>>>(eattr);

    kSplitWT<<<H, H>>>(w12, 0);
    for (int l = 0; l < NL; l++)
        kSplitWT<<<H, H>>>(Wc + (size_t)l * H * H, 1 + l);
    kSplitWT<<<H, H>>>(w3f, 7);

    kDeg0<<<(NN + 255) / 256, 256>>>();
    kHist<<<(NE + 255) / 256, 256>>>(ei);
    kScan<<<1, 1024>>>();
    kScatter<<<(NE + 255) / 256, 256>>>(ei);

    const int SPLB = (NN * H / 8 + 255) / 256;
    dim3 ggrid(H / BN, (NN + BM - 1) / BM);

    kSplitA<<<SPLB, 256>>>(x, 0);
    gemm_mma<<<ggrid, 256>>>(ahi, alo, bhi, blo, h, NN);

    for (int l = 0; l < NL; l++) {
        kSplitA<<<SPLB, 256>>>(h, 0);
        gemm_mma<<<ggrid, 256>>>(ahi, alo,
                                 bhi + (size_t)(1 + l) * H * H,
                                 blo + (size_t)(1 + l) * H * H, hp, NN);
        kSD<<<(NN + 7) / 8, 256>>>(h, l);
        kAlpha<<<(NE + 255) / 256, 256>>>(ei, l);
        kGat<<<(NN + 7) / 8, 256>>>(ei, hp, o, bias + (size_t)l * H);
        float* t = h; h = o; o = t;
    }

    kSplitA<<<SPLB, 256>>>(h, 1);
    gemm_mma<<<ggrid, 256>>>(ahi, alo,
                             bhi + (size_t)7 * H * H,
                             blo + (size_t)7 * H * H, (float*)d_out, NN);
}

// round 7
// speedup vs baseline: 2.4246x; 1.2360x over previous
#include <cuda_runtime.h>
#include <cuda_bf16.h>
#include <cstdint>

#define NN 50000
#define NE 400000
#define H  256
#define ED 768
#define NL 6
#define NEG_SLOPE 0.2f

// ---------------- device scratch ----------------
__device__ __align__(16) float g_h [NN * H];
__device__ __align__(16) float g_hp[NN * H];
__device__ __align__(16) float g_W12[H * H];
__device__ __align__(16) float g_W3f[H * H];
__device__ __align__(16) float g_us[NL * H];
__device__ __align__(16) float g_ud[NL * H];
__device__ __align__(16) float g_ve[NL * ED];
__device__ float g_esc[NL * NE];
__device__ float g_escp[NL * NE];
__device__ int   g_srcp[NE];
__device__ float g_s[NN], g_d[NN];
__device__ float g_s2[NN], g_d2[NN];
__device__ int   g_is64;
__device__ __align__(16) __nv_bfloat16 g_ahi[NN * H];
__device__ __align__(16) __nv_bfloat16 g_alo[NN * H];
__device__ __align__(16) __nv_bfloat16 g_bhi[8 * H * H];
__device__ __align__(16) __nv_bfloat16 g_blo[8 * H * H];
__device__ int g_deg[NN];
__device__ int g_off[NN + 1];
__device__ int g_cur[NN];
__device__ int g_eid[NE];

// ---------------- helpers ----------------
__device__ __forceinline__ long long fetch_idx(const void* ei, long long i, int is64) {
    if (is64) return ((const long long*)ei)[i];
    return (long long)((const int*)ei)[i];
}
__device__ __forceinline__ uint32_t smem_u32(const void* p) {
    uint32_t a;
    asm("{ .reg .u64 t; cvta.to.shared.u64 t, %1; cvt.u32.u64 %0, t; }" : "=r"(a) : "l"(p));
    return a;
}

#define LDM_X4(r, a) \
    asm volatile("ldmatrix.sync.aligned.m8n8.x4.shared.b16 {%0,%1,%2,%3}, [%4];" \
        : "=r"((r)[0]), "=r"((r)[1]), "=r"((r)[2]), "=r"((r)[3]) : "r"(a))

#define MMA16816(d, a, b0, b1) \
    asm volatile("mma.sync.aligned.m16n8k16.row.col.f32.bf16.bf16.f32 " \
        "{%0,%1,%2,%3}, {%4,%5,%6,%7}, {%8,%9}, {%0,%1,%2,%3};" \
        : "+f"((d)[0]), "+f"((d)[1]), "+f"((d)[2]), "+f"((d)[3]) \
        : "r"((a)[0]), "r"((a)[1]), "r"((a)[2]), "r"((a)[3]), "r"(b0), "r"(b1))

#define CP16(dst, src, pb) \
    asm volatile("cp.async.cg.shared.global [%0], [%1], 16, %2;" \
        :: "r"(dst), "l"(src), "r"(pb))
#define CP_COMMIT() asm volatile("cp.async.commit_group;")
#define CP_WAIT(n)  asm volatile("cp.async.wait_group %0;" :: "n"(n))

// ---------------- tiny prep kernels ----------------
__global__ void kDetect(const int* __restrict__ ei) {
    if (blockIdx.x == 0 && threadIdx.x == 0) {
        int nz = 0;
        for (int i = 0; i < 512; i++) nz |= ei[2 * i + 1];
        g_is64 = (nz == 0) ? 1 : 0;
    }
}

__global__ void kW12(const float* __restrict__ W1, const float* __restrict__ W2) {
    int r = blockIdx.x, n = threadIdx.x;
    float acc = 0.f;
    for (int k = 0; k < H; k++) acc += W1[r * H + k] * W2[k * H + n];
    g_W12[r * H + n] = acc;
}

__global__ void kW3f(const float* __restrict__ W3) {
    int r = blockIdx.x, n = threadIdx.x;
    g_W3f[r * H + n] = W3[r * H + n] + W3[(H + r) * H + n];
}

__global__ void kUsUd(const float* __restrict__ Wc, const float* __restrict__ as,
                      const float* __restrict__ ad) {
    int l = blockIdx.x / H, k = blockIdx.x % H;
    int j = threadIdx.x;
    float w = Wc[((size_t)l * H + k) * H + j];
    __shared__ float ss[H], sd[H];
    ss[j] = w * as[l * H + j];
    sd[j] = w * ad[l * H + j];
    __syncthreads();
    for (int st = 128; st > 0; st >>= 1) {
        if (j < st) { ss[j] += ss[j + st]; sd[j] += sd[j + st]; }
        __syncthreads();
    }
    if (j == 0) { g_us[l * H + k] = ss[0]; g_ud[l * H + k] = sd[0]; }
}

__global__ void kVe(const float* __restrict__ We, const float* __restrict__ ae) {
    int l = blockIdx.x / ED, k = blockIdx.x % ED;
    int j = threadIdx.x;
    __shared__ float ss[H];
    ss[j] = We[((size_t)l * ED + k) * H + j] * ae[l * H + j];
    __syncthreads();
    for (int st = 128; st > 0; st >>= 1) {
        if (j < st) ss[j] += ss[j + st];
        __syncthreads();
    }
    if (j == 0) g_ve[l * ED + k] = ss[0];
}

// Edge scores for all 6 layers, one float4 pass over edge_attr (1.23 GB)
__global__ void kEsc(const float* __restrict__ eattr) {
    __shared__ float sV[NL * ED];
    for (int i = threadIdx.x; i < NL * ED; i += blockDim.x) sV[i] = g_ve[i];
    __syncthreads();
    int warp = threadIdx.x >> 5, lane = threadIdx.x & 31;
    int e = blockIdx.x * 8 + warp;
    if (e >= NE) return;
    const float4* row = (const float4*)(eattr + (size_t)e * ED);
    float acc[NL] = {0, 0, 0, 0, 0, 0};
#pragma unroll
    for (int it = 0; it < ED / 128; it++) {
        int j4 = it * 32 + lane;
        float4 a = row[j4];
        int j = j4 * 4;
#pragma unroll
        for (int l = 0; l < NL; l++) {
            const float* v = sV + l * ED + j;
            acc[l] += a.x * v[0] + a.y * v[1] + a.z * v[2] + a.w * v[3];
        }
    }
#pragma unroll
    for (int l = 0; l < NL; l++) {
        float v = acc[l];
        for (int off = 16; off; off >>= 1) v += __shfl_down_sync(0xffffffffu, v, off);
        if (lane == 0) g_esc[(size_t)l * NE + e] = v;
    }
}

// transpose + bf16 split of a 256x256 weight: Bop[n][k] = W[k][n]
__global__ void kSplitWT(const float* __restrict__ W, int bi) {
    int n = blockIdx.x, k = threadIdx.x;
    float v = W[k * H + n];
    __nv_bfloat16 hb = __float2bfloat16(v);
    __nv_bfloat16 lb = __float2bfloat16(v - __bfloat162float(hb));
    size_t o = (size_t)bi * H * H + (size_t)n * H + k;
    g_bhi[o] = hb;
    g_blo[o] = lb;
}

// fp32 activations -> bf16 hi/lo splits
__global__ void kSplitA(const float* __restrict__ src) {
    size_t i = ((size_t)blockIdx.x * 256 + threadIdx.x) * 8;
    if (i >= (size_t)NN * H) return;
    float v[8];
    *(float4*)(v)     = *(const float4*)(src + i);
    *(float4*)(v + 4) = *(const float4*)(src + i + 4);
    union { __nv_bfloat16 b[8]; uint4 u; } hh, ll;
#pragma unroll
    for (int j = 0; j < 8; j++) {
        __nv_bfloat16 hb = __float2bfloat16(v[j]);
        hh.b[j] = hb;
        ll.b[j] = __float2bfloat16(v[j] - __bfloat162float(hb));
    }
    *(uint4*)(g_ahi + i) = hh.u;
    *(uint4*)(g_alo + i) = ll.u;
}

// ---------------- cp.async 2-stage pipelined mma.sync GEMM ----------------
#define BM 128
#define BN 128
#define BK 32
#define PAD 40   // bf16 per smem row (80B); ldmatrix conflict-free
#define OFF_AH 0
#define OFF_AL 10240
#define OFF_BH 20480
#define OFF_BL 30720
#define STAGE_BYTES 40960

__global__ void __launch_bounds__(256, 2) gemm_mma(
    const __nv_bfloat16* __restrict__ Ah, const __nv_bfloat16* __restrict__ Al,
    const __nv_bfloat16* __restrict__ Bh, const __nv_bfloat16* __restrict__ Bl,
    float* __restrict__ C, int M) {
    extern __shared__ char dyn[];
    int tid = threadIdx.x, wid = tid >> 5, lane = tid & 31;
    int wm = wid & 3, wn = wid >> 2;
    int m0 = blockIdx.y * BM, n0 = blockIdx.x * BN;

    float acc[2][8][4];
#pragma unroll
    for (int i = 0; i < 2; i++)
#pragma unroll
        for (int j = 0; j < 8; j++)
#pragma unroll
            for (int q = 0; q < 4; q++) acc[i][j][q] = 0.f;

    int grp = lane >> 3, lr = lane & 7;
    int rowoff = lr + 8 * (grp & 1);
    int csel = grp >> 1;

    // per-thread load coords (2 x 16B per buffer)
    int r0 = tid >> 2, c0 = (tid & 3);           // it=0
    int r1 = (tid + 256) >> 2, c1 = c0;          // it=1

#define LD_STAGE(stg, k0_)                                                     \
    do {                                                                       \
        char* sb = dyn + (stg) * STAGE_BYTES;                                  \
        {                                                                      \
            int gr = m0 + r0;                                                  \
            int pa = (gr < M) ? 16 : 0;                                        \
            int grs = (gr < M) ? gr : 0;                                       \
            uint32_t so = (uint32_t)((r0 * PAD + c0 * 8) * 2);                 \
            CP16(smem_u32(sb + OFF_AH + so), Ah + (size_t)grs * H + (k0_) + c0 * 8, pa); \
            CP16(smem_u32(sb + OFF_AL + so), Al + (size_t)grs * H + (k0_) + c0 * 8, pa); \
            CP16(smem_u32(sb + OFF_BH + so), Bh + (size_t)(n0 + r0) * H + (k0_) + c0 * 8, 16); \
            CP16(smem_u32(sb + OFF_BL + so), Bl + (size_t)(n0 + r0) * H + (k0_) + c0 * 8, 16); \
        }                                                                      \
        {                                                                      \
            int gr = m0 + r1;                                                  \
            int pa = (gr < M) ? 16 : 0;                                        \
            int grs = (gr < M) ? gr : 0;                                       \
            uint32_t so = (uint32_t)((r1 * PAD + c1 * 8) * 2);                 \
            CP16(smem_u32(sb + OFF_AH + so), Ah + (size_t)grs * H + (k0_) + c1 * 8, pa); \
            CP16(smem_u32(sb + OFF_AL + so), Al + (size_t)grs * H + (k0_) + c1 * 8, pa); \
            CP16(smem_u32(sb + OFF_BH + so), Bh + (size_t)(n0 + r1) * H + (k0_) + c1 * 8, 16); \
            CP16(smem_u32(sb + OFF_BL + so), Bl + (size_t)(n0 + r1) * H + (k0_) + c1 * 8, 16); \
        }                                                                      \
        CP_COMMIT();                                                           \
    } while (0)

    LD_STAGE(0, 0);

#pragma unroll
    for (int kt = 0; kt < H / BK; kt++) {
        if (kt + 1 < H / BK) {
            LD_STAGE((kt + 1) & 1, (kt + 1) * BK);
            CP_WAIT(1);
        } else {
            CP_WAIT(0);
        }
        __syncthreads();
        char* sb = dyn + (kt & 1) * STAGE_BYTES;
#pragma unroll
        for (int s = 0; s < 3; s++) {
            char* As = sb + ((s == 2) ? OFF_AL : OFF_AH);
            char* Bs = sb + ((s == 1) ? OFF_BL : OFF_BH);
#pragma unroll
            for (int ks = 0; ks < 2; ks++) {
                int chunk = ks * 2 + csel;
                uint32_t af[2][4], bf[4][4];
#pragma unroll
                for (int mt = 0; mt < 2; mt++) {
                    uint32_t a = smem_u32(As + ((wm * 32 + mt * 16 + rowoff) * PAD + chunk * 8) * 2);
                    LDM_X4(af[mt], a);
                }
#pragma unroll
                for (int nt = 0; nt < 4; nt++) {
                    uint32_t a = smem_u32(Bs + ((wn * 64 + nt * 16 + rowoff) * PAD + chunk * 8) * 2);
                    LDM_X4(bf[nt], a);
                }
#pragma unroll
                for (int mt = 0; mt < 2; mt++)
#pragma unroll
                    for (int nt = 0; nt < 4; nt++) {
                        MMA16816(acc[mt][nt * 2 + 0], af[mt], bf[nt][0], bf[nt][2]);
                        MMA16816(acc[mt][nt * 2 + 1], af[mt], bf[nt][1], bf[nt][3]);
                    }
            }
        }
        __syncthreads();
    }

#pragma unroll
    for (int mt = 0; mt < 2; mt++) {
        int gr = m0 + wm * 32 + mt * 16 + (lane >> 2);
#pragma unroll
        for (int nt = 0; nt < 8; nt++) {
            int gc = n0 + wn * 64 + nt * 8 + (lane & 3) * 2;
            if (gr < M)
                *(float2*)(C + (size_t)gr * H + gc) = make_float2(acc[mt][nt][0], acc[mt][nt][1]);
            if (gr + 8 < M)
                *(float2*)(C + (size_t)(gr + 8) * H + gc) = make_float2(acc[mt][nt][2], acc[mt][nt][3]);
        }
    }
#undef LD_STAGE
}

// ---------------- CSR build ----------------
__global__ void kDeg0() {
    int n = blockIdx.x * 256 + threadIdx.x;
    if (n < NN) g_deg[n] = 0;
}
__global__ void kHist(const void* __restrict__ ei) {
    int e = blockIdx.x * 256 + threadIdx.x;
    if (e >= NE) return;
    long long d = fetch_idx(ei, (long long)NE + e, g_is64);
    atomicAdd(&g_deg[(int)d], 1);
}
__global__ void kScan() {
    __shared__ int ssum[1024];
    int t = threadIdx.x;
    const int per = (NN + 1023) / 1024;
    int b0 = t * per;
    int s = 0;
    for (int i = 0; i < per; i++) {
        int n = b0 + i;
        if (n < NN) s += g_deg[n];
    }
    ssum[t] = s;
    __syncthreads();
    for (int st = 1; st < 1024; st <<= 1) {
        int v = (t >= st) ? ssum[t - st] : 0;
        __syncthreads();
        ssum[t] += v;
        __syncthreads();
    }
    int pre = (t == 0) ? 0 : ssum[t - 1];
    for (int i = 0; i < per; i++) {
        int n = b0 + i;
        if (n < NN) {
            g_off[n] = pre;
            g_cur[n] = pre;
            pre += g_deg[n];
        }
    }
    if (t == 1023) g_off[NN] = ssum[1023];
}
__global__ void kScatter(const void* __restrict__ ei) {
    int e = blockIdx.x * 256 + threadIdx.x;
    if (e >= NE) return;
    long long d = fetch_idx(ei, (long long)NE + e, g_is64);
    int p = atomicAdd(&g_cur[(int)d], 1);
    g_eid[p] = e;
}
// permute esc + src into CSR order
__global__ void kPerm(const void* __restrict__ ei) {
    int j = blockIdx.x * 256 + threadIdx.x;
    if (j >= NE) return;
    int e = g_eid[j];
    g_srcp[j] = (int)fetch_idx(ei, e, g_is64);
#pragma unroll
    for (int l = 0; l < NL; l++)
        g_escp[(size_t)l * NE + j] = g_esc[(size_t)l * NE + e];
}

// splits of h0 + s/d for layer 0 (one pass over h0)
__global__ void kSplitSD(const float* __restrict__ h) {
    int warp = threadIdx.x >> 5, lane = threadIdx.x & 31;
    int n = blockIdx.x * 8 + warp;
    if (n >= NN) return;
    const float4* r = (const float4*)(h + (size_t)n * H);
    float4 v0 = r[lane], v1 = r[lane + 32];
    float o0[4] = {v0.x, v0.y, v0.z, v0.w};
    float o1[4] = {v1.x, v1.y, v1.z, v1.w};
    union { __nv_bfloat16 b[4]; uint2 u; } h0, h1, l0, l1;
#pragma unroll
    for (int q = 0; q < 4; q++) {
        __nv_bfloat16 hb = __float2bfloat16(o0[q]);
        h0.b[q] = hb; l0.b[q] = __float2bfloat16(o0[q] - __bfloat162float(hb));
        hb = __float2bfloat16(o1[q]);
        h1.b[q] = hb; l1.b[q] = __float2bfloat16(o1[q] - __bfloat162float(hb));
    }
    *(uint2*)(g_ahi + (size_t)n * H + lane * 4)       = h0.u;
    *(uint2*)(g_ahi + (size_t)n * H + (lane + 32) * 4) = h1.u;
    *(uint2*)(g_alo + (size_t)n * H + lane * 4)       = l0.u;
    *(uint2*)(g_alo + (size_t)n * H + (lane + 32) * 4) = l1.u;
    const float4* u4 = (const float4*)g_us;
    const float4* v4 = (const float4*)g_ud;
    float4 ua = u4[lane], ub = u4[lane + 32];
    float4 va = v4[lane], vb = v4[lane + 32];
    float s = o0[0]*ua.x + o0[1]*ua.y + o0[2]*ua.z + o0[3]*ua.w
            + o1[0]*ub.x + o1[1]*ub.y + o1[2]*ub.z + o1[3]*ub.w;
    float d = o0[0]*va.x + o0[1]*va.y + o0[2]*va.z + o0[3]*va.w
            + o1[0]*vb.x + o1[1]*vb.y + o1[2]*vb.z + o1[3]*vb.w;
    for (int off = 16; off; off >>= 1) {
        s += __shfl_down_sync(0xffffffffu, s, off);
        d += __shfl_down_sync(0xffffffffu, d, off);
    }
    if (lane == 0) { g_s[n] = s; g_d[n] = d; }
}

// mega-fused GAT layer: inline alpha + segment softmax + gather + bias
// + bf16 splits of output + next-layer s/d.  Warp per node, zero atomics.
__global__ void kGatF(const float* __restrict__ hp,
                      const float* __restrict__ s_cur, const float* __restrict__ d_cur,
                      float* __restrict__ s_nxt, float* __restrict__ d_nxt,
                      const float* __restrict__ escp_l,
                      const float* __restrict__ bias,
                      const float* __restrict__ usn, const float* __restrict__ udn,
                      int relu) {
    int warp = threadIdx.x >> 5, lane = threadIdx.x & 31;
    int n = blockIdx.x * 8 + warp;
    if (n >= NN) return;
    int beg = g_off[n], end = g_off[n + 1];
    float dn = d_cur[n];
    float m = -1e30f;
    for (int j0 = beg; j0 < end; j0 += 32) {
        int j = j0 + lane;
        float a = -1e30f;
        if (j < end) {
            float t = s_cur[g_srcp[j]] + dn + escp_l[j];
            a = (t > 0.f) ? t : NEG_SLOPE * t;
        }
        m = fmaxf(m, a);
    }
    for (int o = 16; o; o >>= 1) m = fmaxf(m, __shfl_xor_sync(0xffffffffu, m, o));

    float4 a0 = make_float4(0, 0, 0, 0), a1 = make_float4(0, 0, 0, 0);
    float den = 0.f;
    for (int j0 = beg; j0 < end; j0 += 32) {
        int j = j0 + lane;
        float w = 0.f;
        int sj = 0;
        if (j < end) {
            sj = g_srcp[j];
            float t = s_cur[sj] + dn + escp_l[j];
            t = (t > 0.f) ? t : NEG_SLOPE * t;
            w = __expf(t - m);
            den += w;
        }
        int cnt = min(32, end - j0);
        for (int i = 0; i < cnt; i++) {
            float wi = __shfl_sync(0xffffffffu, w, i);
            int si = __shfl_sync(0xffffffffu, sj, i);
            const float4* r = (const float4*)(hp + (size_t)si * H);
            float4 v0 = r[lane], v1 = r[lane + 32];
            a0.x += wi * v0.x; a0.y += wi * v0.y; a0.z += wi * v0.z; a0.w += wi * v0.w;
            a1.x += wi * v1.x; a1.y += wi * v1.y; a1.z += wi * v1.z; a1.w += wi * v1.w;
        }
    }
    for (int o = 16; o; o >>= 1) den += __shfl_xor_sync(0xffffffffu, den, o);
    float sc = 1.f / (den + 1e-16f);

    const float4* b4 = (const float4*)bias;
    float4 b0 = b4[lane], b1 = b4[lane + 32];
    float o0[4] = {a0.x * sc + b0.x, a0.y * sc + b0.y, a0.z * sc + b0.z, a0.w * sc + b0.w};
    float o1[4] = {a1.x * sc + b1.x, a1.y * sc + b1.y, a1.z * sc + b1.z, a1.w * sc + b1.w};
    float p0[4], p1[4];
#pragma unroll
    for (int q = 0; q < 4; q++) {
        p0[q] = relu ? fmaxf(o0[q], 0.f) : o0[q];
        p1[q] = relu ? fmaxf(o1[q], 0.f) : o1[q];
    }
    union { __nv_bfloat16 b[4]; uint2 u; } h0, h1, l0, l1;
#pragma unroll
    for (int q = 0; q < 4; q++) {
        __nv_bfloat16 hb = __float2bfloat16(p0[q]);
        h0.b[q] = hb; l0.b[q] = __float2bfloat16(p0[q] - __bfloat162float(hb));
        hb = __float2bfloat16(p1[q]);
        h1.b[q] = hb; l1.b[q] = __float2bfloat16(p1[q] - __bfloat162float(hb));
    }
    *(uint2*)(g_ahi + (size_t)n * H + lane * 4)        = h0.u;
    *(uint2*)(g_ahi + (size_t)n * H + (lane + 32) * 4) = h1.u;
    *(uint2*)(g_alo + (size_t)n * H + lane * 4)        = l0.u;
    *(uint2*)(g_alo + (size_t)n * H + (lane + 32) * 4) = l1.u;

    if (usn) {
        const float4* u4 = (const float4*)usn;
        const float4* v4 = (const float4*)udn;
        float4 ua = u4[lane], ub = u4[lane + 32];
        float4 va = v4[lane], vb = v4[lane + 32];
        float s = o0[0]*ua.x + o0[1]*ua.y + o0[2]*ua.z + o0[3]*ua.w
                + o1[0]*ub.x + o1[1]*ub.y + o1[2]*ub.z + o1[3]*ub.w;
        float d = o0[0]*va.x + o0[1]*va.y + o0[2]*va.z + o0[3]*va.w
                + o1[0]*vb.x + o1[1]*vb.y + o1[2]*vb.z + o1[3]*vb.w;
        for (int o = 16; o; o >>= 1) {
            s += __shfl_down_sync(0xffffffffu, s, o);
            d += __shfl_down_sync(0xffffffffu, d, o);
        }
        if (lane == 0) { s_nxt[n] = s; d_nxt[n] = d; }
    }
}

// ---------------- launch ----------------
extern "C" void kernel_launch(void* const* d_in, const int* in_sizes, int n_in,
                              void* d_out, int out_size) {
    const float* x     = (const float*)d_in[0];
    const void*  ei    = d_in[1];
    const float* eattr = (const float*)d_in[2];
    const float* W1    = (const float*)d_in[3];
    const float* W2    = (const float*)d_in[4];
    const float* Wc    = (const float*)d_in[5];
    const float* We    = (const float*)d_in[6];
    const float* as    = (const float*)d_in[7];
    const float* ad    = (const float*)d_in[8];
    const float* ae    = (const float*)d_in[9];
    const float* bias  = (const float*)d_in[10];
    const float* W3    = (const float*)d_in[11];

    float *h, *hp, *w12, *w3f, *us, *ud, *sA, *dA, *sB, *dB, *escp;
    __nv_bfloat16 *ahi, *alo, *bhi, *blo;
    cudaGetSymbolAddress((void**)&h,    g_h);
    cudaGetSymbolAddress((void**)&hp,   g_hp);
    cudaGetSymbolAddress((void**)&w12,  g_W12);
    cudaGetSymbolAddress((void**)&w3f,  g_W3f);
    cudaGetSymbolAddress((void**)&us,   g_us);
    cudaGetSymbolAddress((void**)&ud,   g_ud);
    cudaGetSymbolAddress((void**)&sA,   g_s);
    cudaGetSymbolAddress((void**)&dA,   g_d);
    cudaGetSymbolAddress((void**)&sB,   g_s2);
    cudaGetSymbolAddress((void**)&dB,   g_d2);
    cudaGetSymbolAddress((void**)&escp, g_escp);
    cudaGetSymbolAddress((void**)&ahi,  g_ahi);
    cudaGetSymbolAddress((void**)&alo,  g_alo);
    cudaGetSymbolAddress((void**)&bhi,  g_bhi);
    cudaGetSymbolAddress((void**)&blo,  g_blo);

    cudaFuncSetAttribute(gemm_mma, cudaFuncAttributeMaxDynamicSharedMemorySize,
                         2 * STAGE_BYTES);

    const int SPLB = (NN * H / 8 + 255) / 256;
    dim3 ggrid(H / BN, (NN + BM - 1) / BM);

    // launch order puts gemm_mma at position 4 for the ncu -s window
    kW12<<<H, H>>>(W1, W2);
    kSplitWT<<<H, H>>>(w12, 0);
    kSplitA<<<SPLB, 256>>>(x);
    gemm_mma<<<ggrid, 256, 2 * STAGE_BYTES>>>(ahi, alo, bhi, blo, h, NN);

    kDetect<<<1, 32>>>((const int*)ei);
    kW3f<<<H, H>>>(W3);
    kUsUd<<<NL * H, H>>>(Wc, as, ad);
    kVe<<<NL * ED, H>>>(We, ae);
    kEsc<<<(NE + 7) / 8, 256>>>(eattr);
    for (int l = 0; l < NL; l++)
        kSplitWT<<<H, H>>>(Wc + (size_t)l * H * H, 1 + l);
    kSplitWT<<<H, H>>>(w3f, 7);

    kDeg0<<<(NN + 255) / 256, 256>>>();
    kHist<<<(NE + 255) / 256, 256>>>(ei);
    kScan<<<1, 1024>>>();
    kScatter<<<(NE + 255) / 256, 256>>>(ei);
    kPerm<<<(NE + 255) / 256, 256>>>(ei);

    kSplitSD<<<(NN + 7) / 8, 256>>>(h);   // splits of h0 + s/d for layer 0

    float *sc = sA, *dc = dA, *sn = sB, *dn = dB;
    for (int l = 0; l < NL; l++) {
        gemm_mma<<<ggrid, 256, 2 * STAGE_BYTES>>>(ahi, alo,
            bhi + (size_t)(1 + l) * H * H, blo + (size_t)(1 + l) * H * H, hp, NN);
        const float* usn = (l + 1 < NL) ? (us + (size_t)(l + 1) * H) : nullptr;
        const float* udn = (l + 1 < NL) ? (ud + (size_t)(l + 1) * H) : nullptr;
        kGatF<<<(NN + 7) / 8, 256>>>(hp, sc, dc, sn, dn,
                                     escp + (size_t)l * NE, bias + (size_t)l * H,
                                     usn, udn, (l == NL - 1) ? 1 : 0);
        float* t;
        t = sc; sc = sn; sn = t;
        t = dc; dc = dn; dn = t;
    }

    gemm_mma<<<ggrid, 256, 2 * STAGE_BYTES>>>(ahi, alo,
        bhi + (size_t)7 * H * H, blo + (size_t)7 * H * H, (float*)d_out, NN);
}